// round 14
// baseline (speedup 1.0000x reference)
#include <cuda_runtime.h>
#include <cuda_bf16.h>
#include <cstdint>
#include <math.h>

// ---------------------------------------------------------------------------
// Problem constants
// ---------------------------------------------------------------------------
#define BATCH 8
#define CIN   128
#define HH    96
#define WW    96
#define PP    (HH*WW)          // 9216
#define RSQRT_D 0.17677669529663687f

// t layout: [b][g][qkv][p][d]  (d=32 contiguous per position)
__device__ float g_t[(size_t)BATCH * 384 * PP];

// Pre-split W in smem-image layout: [slab(6)][hi/lo(2)][64 rows x 136 bf16]
__device__ __nv_bfloat16 g_wslab[6][2][64 * 136];

// ---------------------------------------------------------------------------
// GEMM smem layout (64-p tile: X 34KB + W 34KB = 68KB -> 3 CTAs/SM)
// ---------------------------------------------------------------------------
static constexpr int TS   = 136;        // bf16 elems per row
static constexpr int TSB  = TS * 2;     // 272 bytes
static constexpr int XHI  = 0;                  // 64 rows -> 17408 B
static constexpr int XLO  = 64 * TSB;           // 17408
static constexpr int WBUF = 2 * 64 * TSB;       // 34816 (hi 17408 | lo 17408)
static constexpr int WLO_OFF = 64 * TSB;        // 17408
static constexpr int WSLAB_BYTES = 2 * 64 * TSB;  // 34816
static constexpr int GEMM_SMEM = WBUF + WSLAB_BYTES; // 69632 B

__device__ __forceinline__ uint32_t smem_u32(const void* p) {
    uint32_t a;
    asm("{ .reg .u64 t; cvta.to.shared.u64 t, %1; cvt.u32.u64 %0, t; }" : "=r"(a) : "l"(p));
    return a;
}
__device__ __forceinline__ void ldm_x4(uint32_t r[4], uint32_t a) {
    asm volatile("ldmatrix.sync.aligned.m8n8.x4.shared.b16 {%0,%1,%2,%3}, [%4];"
                 : "=r"(r[0]), "=r"(r[1]), "=r"(r[2]), "=r"(r[3]) : "r"(a));
}
__device__ __forceinline__ void mma16816(float* c, const uint32_t* a, const uint32_t* b) {
    asm volatile("mma.sync.aligned.m16n8k16.row.col.f32.bf16.bf16.f32 "
                 "{%0,%1,%2,%3}, {%4,%5,%6,%7}, {%8,%9}, {%0,%1,%2,%3};"
                 : "+f"(c[0]), "+f"(c[1]), "+f"(c[2]), "+f"(c[3])
                 : "r"(a[0]), "r"(a[1]), "r"(a[2]), "r"(a[3]), "r"(b[0]), "r"(b[1]));
}
__device__ __forceinline__ void cp16(uint32_t dst, const void* src) {
    asm volatile("cp.async.ca.shared.global [%0], [%1], 16;" :: "r"(dst), "l"(src));
}
// cp.async with src-size predication: sz=0 -> zero-fill (src not read)
__device__ __forceinline__ void cp16z(uint32_t dst, const void* src, bool ok) {
    int sz = ok ? 16 : 0;
    asm volatile("cp.async.ca.shared.global [%0], [%1], 16, %2;"
                 :: "r"(dst), "l"(src), "r"(sz));
}
__device__ __forceinline__ void cp_commit() {
    asm volatile("cp.async.commit_group;" ::: "memory");
}
__device__ __forceinline__ void cp_wait0() {
    asm volatile("cp.async.wait_group 0;" ::: "memory");
}
// split two fp32 into packed bf16x2 hi + lo (lo = residual)
__device__ __forceinline__ void split2(float f0, float f1, uint32_t& hi, uint32_t& lo) {
    __nv_bfloat16 h0 = __float2bfloat16(f0);
    __nv_bfloat16 h1 = __float2bfloat16(f1);
    __nv_bfloat16 l0 = __float2bfloat16(f0 - __bfloat162float(h0));
    __nv_bfloat16 l1 = __float2bfloat16(f1 - __bfloat162float(h1));
    hi = ((uint32_t)*reinterpret_cast<uint16_t*>(&h1) << 16) | *reinterpret_cast<uint16_t*>(&h0);
    lo = ((uint32_t)*reinterpret_cast<uint16_t*>(&l1) << 16) | *reinterpret_cast<uint16_t*>(&l0);
}

// ---------------------------------------------------------------------------
// Kernel 0: pre-split W into smem-image layout
// ---------------------------------------------------------------------------
__global__ void wprep_kernel(const float* __restrict__ Wt) {
    int i = blockIdx.x * 256 + threadIdx.x;      // over 384*64 channel-pairs
    if (i < 384 * 64) {
        int o = i >> 6, cp = i & 63;
        float2 w = *reinterpret_cast<const float2*>(&Wt[o * 128 + 2 * cp]);
        uint32_t hi, lo;
        split2(w.x, w.y, hi, lo);
        int slab = o >> 6, row = o & 63;
        reinterpret_cast<uint32_t*>(g_wslab[slab][0])[row * 68 + cp] = hi;
        reinterpret_cast<uint32_t*>(g_wslab[slab][1])[row * 68 + cp] = lo;
    }
}

// ---------------------------------------------------------------------------
// Kernel A: QKV GEMM via mma.sync bf16 (3-term hi/lo split, fp32 accum).
// 64-p tile, 3 CTAs/SM. 8 warps = 2(p) x 4(o); warp tile 32p x 16o.
// Grid: (144 p-tiles, 8 batches).
// ---------------------------------------------------------------------------
__global__ __launch_bounds__(256, 3) void qkv_mma(const float* __restrict__ x) {
    extern __shared__ char smc[];
    const uint32_t smb = smem_u32(smc);
    const int tid = threadIdx.x;
    const int p0  = blockIdx.x * 64;
    const int b   = blockIdx.y;

    // ---- Prologue: issue cp.async for W slab 0 ----
    {
        const char* src = reinterpret_cast<const char*>(g_wslab[0]);
        for (int i = tid; i < WSLAB_BYTES / 16; i += 256)
            cp16(smb + WBUF + i * 16, src + i * 16);
        cp_commit();
    }

    // ---- Stage X^T (hi/lo): thread handles quarter p-row (32 channels) ----
    {
        const int row = tid & 63;
        const int qtr = tid >> 6;            // 0..3
        const float* xp = x + (size_t)b * CIN * PP + p0 + row;
        uint32_t* xh = reinterpret_cast<uint32_t*>(smc + XHI + row * TSB + qtr * 64);
        uint32_t* xl = reinterpret_cast<uint32_t*>(smc + XLO + row * TSB + qtr * 64);
#pragma unroll
        for (int j = 0; j < 16; j++) {
            int c = qtr * 32 + 2 * j;
            float f0 = xp[(size_t)c * PP];
            float f1 = xp[(size_t)(c + 1) * PP];
            uint32_t hi, lo;
            split2(f0, f1, hi, lo);
            xh[j] = hi;
            xl[j] = lo;
        }
    }

    const int lane = tid & 31, wid = tid >> 5;
    const int wp = wid & 1;          // p: 2 x 32
    const int wo = wid >> 1;         // o: 4 x 16
    const int sel = lane >> 3, idx = lane & 7;
    const int gid = lane >> 2, tig = lane & 3;

    const uint32_t aoff = (uint32_t)((idx + (sel & 1) * 8) * TSB + (sel >> 1) * 16);
    const uint32_t boff = (uint32_t)((idx + (sel >> 1) * 8) * TSB + (sel & 1) * 16);
    const uint32_t aHi = smb + XHI + wp * 32 * TSB + aoff;
    const uint32_t aLo = smb + XLO + wp * 32 * TSB + aoff;
    const uint32_t bHi = smb + WBUF + wo * 16 * TSB + boff;
    const uint32_t bLo = bHi + WLO_OFF;

    for (int s = 0; s < 6; s++) {
        cp_wait0();
        __syncthreads();             // W slab visible to all warps (& X on s=0)

        float C[2][2][4];
#pragma unroll
        for (int mf = 0; mf < 2; mf++)
#pragma unroll
            for (int nf = 0; nf < 2; nf++)
#pragma unroll
                for (int r = 0; r < 4; r++) C[mf][nf][r] = 0.f;

#pragma unroll
        for (int ks = 0; ks < 8; ks++) {
            const uint32_t ko = ks * 32;
            uint32_t Ah[2][4], Al[2][4], Bh[4], Bl[4];
#pragma unroll
            for (int mf = 0; mf < 2; mf++) {
                ldm_x4(Ah[mf], aHi + mf * 16 * TSB + ko);
                ldm_x4(Al[mf], aLo + mf * 16 * TSB + ko);
            }
            ldm_x4(Bh, bHi + ko);
            ldm_x4(Bl, bLo + ko);
#pragma unroll
            for (int mf = 0; mf < 2; mf++) {
#pragma unroll
                for (int nf = 0; nf < 2; nf++) {
                    const uint32_t* bh = &Bh[nf * 2];
                    const uint32_t* bl = &Bl[nf * 2];
                    mma16816(C[mf][nf], Ah[mf], bh);   // hh
                    mma16816(C[mf][nf], Ah[mf], bl);   // hl
                    mma16816(C[mf][nf], Al[mf], bh);   // lh
                }
            }
        }

        __syncthreads();             // all warps done reading WBUF
        if (s < 5) {                 // stream next slab while epilogue runs
            const char* src = reinterpret_cast<const char*>(g_wslab[s + 1]);
            for (int i = tid; i < WSLAB_BYTES / 16; i += 256)
                cp16(smb + WBUF + i * 16, src + i * 16);
            cp_commit();
        }

        // ---- Epilogue: t[b][g][ot][p][d], d-contiguous float2 stores ----
        const int ot = s >> 1;
#pragma unroll
        for (int mf = 0; mf < 2; mf++) {
#pragma unroll
            for (int nf = 0; nf < 2; nf++) {
                const int p_l = wp * 32 + mf * 16 + gid;
                const int oo  = (s & 1) * 64 + wo * 16 + nf * 8 + tig * 2;
                const int g   = oo >> 5;
                const int d   = oo & 31;
                float* dst = g_t + (((size_t)(b * 4 + g) * 3 + ot) * PP + p0 + p_l) * 32 + d;
                *reinterpret_cast<float2*>(dst) = make_float2(C[mf][nf][0], C[mf][nf][1]);
                *reinterpret_cast<float2*>(dst + 8 * 32) = make_float2(C[mf][nf][2], C[mf][nf][3]);
            }
        }
    }
}

// ---------------------------------------------------------------------------
// Kernel B: 3x3 neighborhood attention (frozen from round 12).
// CTA = 32x8 tile, 256 threads; one 34x10x36f halo buffer reused K then V.
// ---------------------------------------------------------------------------
static constexpr int TW = 32, TH = 8;      // tile width / height
static constexpr int HW = 34, HHALO = 10;  // halo width / height
static constexpr int HALO = HW * HHALO;    // 340
static constexpr int HPAD = 36;
static constexpr int ATT_SMEM = HALO * HPAD * 4;   // 48960 B

__device__ __forceinline__ void load_halo_async(uint32_t smb, const float* __restrict__ src,
                                                int ty0, int tx0, int tid) {
    for (int i = tid; i < HALO * 8; i += 256) {
        int pos = i >> 3, c = i & 7;
        int yy = pos / HW;
        int xx = pos - yy * HW;
        int gy = ty0 - 1 + yy;
        int gx = tx0 - 1 + xx;
        bool ok = (gy >= 0) && (gy < HH) && (gx >= 0) && (gx < WW);
        int cgy = ok ? gy : 0, cgx = ok ? gx : 0;    // clamped (unused if !ok)
        const float* sp = src + ((size_t)(cgy * WW + cgx)) * 32 + c * 4;
        cp16z(smb + (uint32_t)(pos * HPAD + c * 4) * 4, sp, ok);
    }
    cp_commit();
}

__global__ __launch_bounds__(256, 4) void attn_kernel(float* __restrict__ out) {
    extern __shared__ char smc[];
    float* smf = reinterpret_cast<float*>(smc);
    const uint32_t smb = smem_u32(smc);
    const int tid  = threadIdx.x;
    const int tile = blockIdx.x;               // 36 tiles: 3 x-wise, 12 y-wise
    const int ty0  = (tile / 3) * TH;
    const int tx0  = (tile % 3) * TW;
    const int g    = blockIdx.y;
    const int b    = (BATCH - 1) - blockIdx.z; // reversed: freshest t first
    const int tx = tid & 31;
    const int ty = tid >> 5;

    const size_t hb = (size_t)(b * 4 + g) * 3;
    const float* qb = g_t + (hb + 0) * PP * 32;
    const float* kb = g_t + (hb + 1) * PP * 32;
    const float* vb = g_t + (hb + 2) * PP * 32;

    load_halo_async(smb, kb, ty0, tx0, tid);     // K halo in flight

    const float* qp = qb + ((size_t)((ty0 + ty) * WW + tx0 + tx)) * 32;
    float4 q4[8];
#pragma unroll
    for (int j = 0; j < 8; j++) q4[j] = *reinterpret_cast<const float4*>(qp + 4 * j);

    int hp9[9];
#pragma unroll
    for (int n = 0; n < 9; n++) hp9[n] = (ty + n / 3) * HW + tx + (n % 3);

    cp_wait0();
    __syncthreads();

    float att[9];
#pragma unroll
    for (int n = 0; n < 9; n++) {
        const float* kp = smf + hp9[n] * HPAD;
        float sx = 0.f, sy = 0.f, sz = 0.f, sw = 0.f;
#pragma unroll
        for (int j = 0; j < 8; j++) {
            float4 kv = *reinterpret_cast<const float4*>(kp + 4 * j);
            sx = fmaf(q4[j].x, kv.x, sx);
            sy = fmaf(q4[j].y, kv.y, sy);
            sz = fmaf(q4[j].z, kv.z, sz);
            sw = fmaf(q4[j].w, kv.w, sw);
        }
        att[n] = ((sx + sy) + (sz + sw)) * RSQRT_D;
    }

    float m = att[0];
#pragma unroll
    for (int n = 1; n < 9; n++) m = fmaxf(m, att[n]);
    float ssum = 0.f;
#pragma unroll
    for (int n = 0; n < 9; n++) { att[n] = __expf(att[n] - m); ssum += att[n]; }
    float inv = 1.f / ssum;
#pragma unroll
    for (int n = 0; n < 9; n++) att[n] *= inv;

    __syncthreads();                 // everyone done reading K
    load_halo_async(smb, vb, ty0, tx0, tid);
    cp_wait0();
    __syncthreads();

    float* op = out + ((size_t)(b * CIN + g * 32)) * PP + (ty0 + ty) * WW + tx0 + tx;
#pragma unroll
    for (int j = 0; j < 8; j++) {
        float4 acc = make_float4(0.f, 0.f, 0.f, 0.f);
#pragma unroll
        for (int n = 0; n < 9; n++) {
            float4 vv = *reinterpret_cast<const float4*>(smf + hp9[n] * HPAD + 4 * j);
            acc.x = fmaf(att[n], vv.x, acc.x);
            acc.y = fmaf(att[n], vv.y, acc.y);
            acc.z = fmaf(att[n], vv.z, acc.z);
            acc.w = fmaf(att[n], vv.w, acc.w);
        }
        op[(size_t)(4 * j + 0) * PP] = acc.x;
        op[(size_t)(4 * j + 1) * PP] = acc.y;
        op[(size_t)(4 * j + 2) * PP] = acc.z;
        op[(size_t)(4 * j + 3) * PP] = acc.w;
    }
}

// ---------------------------------------------------------------------------
extern "C" void kernel_launch(void* const* d_in, const int* in_sizes, int n_in,
                              void* d_out, int out_size) {
    const float* x  = (const float*)d_in[0];   // [8,128,96,96]
    const float* Wt = (const float*)d_in[1];   // [384,128]
    float* out = (float*)d_out;                // [8,128,96,96]

    cudaFuncSetAttribute(qkv_mma,    cudaFuncAttributeMaxDynamicSharedMemorySize, GEMM_SMEM);
    cudaFuncSetAttribute(attn_kernel, cudaFuncAttributeMaxDynamicSharedMemorySize, ATT_SMEM);

    wprep_kernel<<<(384 * 64 + 255) / 256, 256>>>(Wt);
    qkv_mma<<<dim3(PP / 64, BATCH), 256, GEMM_SMEM>>>(x);
    attn_kernel<<<dim3((WW / TW) * (HH / TH), 4, BATCH), 256, ATT_SMEM>>>(out);
}

// round 15
// speedup vs baseline: 1.0750x; 1.0750x over previous
#include <cuda_runtime.h>
#include <cuda_bf16.h>
#include <cstdint>
#include <math.h>

// ---------------------------------------------------------------------------
// Problem constants
// ---------------------------------------------------------------------------
#define BATCH 8
#define CIN   128
#define HH    96
#define WW    96
#define PP    (HH*WW)          // 9216
#define RSQRT_D 0.17677669529663687f

// t layout: [b][g][qkv][p][d]  (d=32 contiguous per position)
__device__ float g_t[(size_t)BATCH * 384 * PP];

// Pre-split W in smem-image layout: [slab(6)][hi/lo(2)][64 rows x 136 bf16]
__device__ __nv_bfloat16 g_wslab[6][2][64 * 136];

// ---------------------------------------------------------------------------
// GEMM smem layout (single W buffer -> 102 KB -> 2 CTAs/SM)
// ---------------------------------------------------------------------------
static constexpr int TS   = 136;        // bf16 elems per row
static constexpr int TSB  = TS * 2;     // 272 bytes
static constexpr int XHI  = 0;                  // 34816 B
static constexpr int XLO  = 128 * TSB;          // 34816
static constexpr int WBUF = 2 * 128 * TSB;      // 69632 (hi 17408 | lo 17408)
static constexpr int WLO_OFF = 64 * TSB;        // 17408
static constexpr int WSLAB_BYTES = 2 * 64 * TSB;  // 34816
static constexpr int GEMM_SMEM = WBUF + WSLAB_BYTES; // 104448 B

__device__ __forceinline__ uint32_t smem_u32(const void* p) {
    uint32_t a;
    asm("{ .reg .u64 t; cvta.to.shared.u64 t, %1; cvt.u32.u64 %0, t; }" : "=r"(a) : "l"(p));
    return a;
}
__device__ __forceinline__ void ldm_x4(uint32_t r[4], uint32_t a) {
    asm volatile("ldmatrix.sync.aligned.m8n8.x4.shared.b16 {%0,%1,%2,%3}, [%4];"
                 : "=r"(r[0]), "=r"(r[1]), "=r"(r[2]), "=r"(r[3]) : "r"(a));
}
__device__ __forceinline__ void mma16816(float* c, const uint32_t* a, const uint32_t* b) {
    asm volatile("mma.sync.aligned.m16n8k16.row.col.f32.bf16.bf16.f32 "
                 "{%0,%1,%2,%3}, {%4,%5,%6,%7}, {%8,%9}, {%0,%1,%2,%3};"
                 : "+f"(c[0]), "+f"(c[1]), "+f"(c[2]), "+f"(c[3])
                 : "r"(a[0]), "r"(a[1]), "r"(a[2]), "r"(a[3]), "r"(b[0]), "r"(b[1]));
}
__device__ __forceinline__ void cp16(uint32_t dst, const void* src) {
    asm volatile("cp.async.ca.shared.global [%0], [%1], 16;" :: "r"(dst), "l"(src));
}
// cp.async with src-size predication: sz=0 -> zero-fill (src not read)
__device__ __forceinline__ void cp16z(uint32_t dst, const void* src, bool ok) {
    int sz = ok ? 16 : 0;
    asm volatile("cp.async.ca.shared.global [%0], [%1], 16, %2;"
                 :: "r"(dst), "l"(src), "r"(sz));
}
__device__ __forceinline__ void cp_commit() {
    asm volatile("cp.async.commit_group;" ::: "memory");
}
__device__ __forceinline__ void cp_wait0() {
    asm volatile("cp.async.wait_group 0;" ::: "memory");
}
// split two fp32 into packed bf16x2 hi + lo (lo = residual)
__device__ __forceinline__ void split2(float f0, float f1, uint32_t& hi, uint32_t& lo) {
    __nv_bfloat16 h0 = __float2bfloat16(f0);
    __nv_bfloat16 h1 = __float2bfloat16(f1);
    __nv_bfloat16 l0 = __float2bfloat16(f0 - __bfloat162float(h0));
    __nv_bfloat16 l1 = __float2bfloat16(f1 - __bfloat162float(h1));
    hi = ((uint32_t)*reinterpret_cast<uint16_t*>(&h1) << 16) | *reinterpret_cast<uint16_t*>(&h0);
    lo = ((uint32_t)*reinterpret_cast<uint16_t*>(&l1) << 16) | *reinterpret_cast<uint16_t*>(&l0);
}

// ---------------------------------------------------------------------------
// Kernel 0: pre-split W into smem-image layout
// ---------------------------------------------------------------------------
__global__ void wprep_kernel(const float* __restrict__ Wt) {
    int i = blockIdx.x * 256 + threadIdx.x;      // over 384*64 channel-pairs
    if (i < 384 * 64) {
        int o = i >> 6, cp = i & 63;
        float2 w = *reinterpret_cast<const float2*>(&Wt[o * 128 + 2 * cp]);
        uint32_t hi, lo;
        split2(w.x, w.y, hi, lo);
        int slab = o >> 6, row = o & 63;
        reinterpret_cast<uint32_t*>(g_wslab[slab][0])[row * 68 + cp] = hi;
        reinterpret_cast<uint32_t*>(g_wslab[slab][1])[row * 68 + cp] = lo;
    }
}

// ---------------------------------------------------------------------------
// Kernel A: QKV GEMM via mma.sync bf16 (3-term hi/lo split, fp32 accum).
// Single W buffer, 2 CTAs/SM; W staging hidden by co-resident CTA.
// 8 warps = 4(p) x 2(o); warp tile 32p x 32o. Grid: (72, 8).
// ---------------------------------------------------------------------------
__global__ __launch_bounds__(256, 2) void qkv_mma(const float* __restrict__ x) {
    extern __shared__ char smc[];
    const uint32_t smb = smem_u32(smc);
    const int tid = threadIdx.x;
    const int p0  = blockIdx.x * 128;
    const int b   = blockIdx.y;

    // ---- Prologue: issue cp.async for W slab 0 ----
    {
        const char* src = reinterpret_cast<const char*>(g_wslab[0]);
        for (int i = tid; i < WSLAB_BYTES / 16; i += 256)
            cp16(smb + WBUF + i * 16, src + i * 16);
        cp_commit();
    }

    // ---- Stage X^T (hi/lo): thread handles half a p-row (64 channels) ----
    {
        const int row  = tid & 127;
        const int half = tid >> 7;
        const float* xp = x + (size_t)b * CIN * PP + p0 + row;
        uint32_t* xh = reinterpret_cast<uint32_t*>(smc + XHI + row * TSB + half * 128);
        uint32_t* xl = reinterpret_cast<uint32_t*>(smc + XLO + row * TSB + half * 128);
#pragma unroll
        for (int j = 0; j < 32; j++) {
            int c = half * 64 + 2 * j;
            float f0 = xp[(size_t)c * PP];
            float f1 = xp[(size_t)(c + 1) * PP];
            uint32_t hi, lo;
            split2(f0, f1, hi, lo);
            xh[j] = hi;
            xl[j] = lo;
        }
    }

    const int lane = tid & 31, wid = tid >> 5;
    const int wp = wid & 3;          // p: 4 x 32
    const int wo = wid >> 2;         // o: 2 x 32
    const int sel = lane >> 3, idx = lane & 7;
    const int gid = lane >> 2, tig = lane & 3;

    const uint32_t aoff = (uint32_t)((idx + (sel & 1) * 8) * TSB + (sel >> 1) * 16);
    const uint32_t boff = (uint32_t)((idx + (sel >> 1) * 8) * TSB + (sel & 1) * 16);
    const uint32_t aHi = smb + XHI + wp * 32 * TSB + aoff;
    const uint32_t aLo = smb + XLO + wp * 32 * TSB + aoff;
    const uint32_t bHi = smb + WBUF + wo * 32 * TSB + boff;
    const uint32_t bLo = bHi + WLO_OFF;

    for (int s = 0; s < 6; s++) {
        cp_wait0();
        __syncthreads();             // W slab visible to all warps (& X on s=0)

        float C[2][4][4];
#pragma unroll
        for (int mf = 0; mf < 2; mf++)
#pragma unroll
            for (int nf = 0; nf < 4; nf++)
#pragma unroll
                for (int r = 0; r < 4; r++) C[mf][nf][r] = 0.f;

#pragma unroll
        for (int ks = 0; ks < 8; ks++) {
            const uint32_t ko = ks * 32;
            uint32_t Ah[2][4], Al[2][4], Bh[2][4], Bl[2][4];
#pragma unroll
            for (int mf = 0; mf < 2; mf++) {
                ldm_x4(Ah[mf], aHi + mf * 16 * TSB + ko);
                ldm_x4(Al[mf], aLo + mf * 16 * TSB + ko);
            }
#pragma unroll
            for (int np = 0; np < 2; np++) {
                ldm_x4(Bh[np], bHi + np * 16 * TSB + ko);
                ldm_x4(Bl[np], bLo + np * 16 * TSB + ko);
            }
#pragma unroll
            for (int mf = 0; mf < 2; mf++) {
#pragma unroll
                for (int nf = 0; nf < 4; nf++) {
                    const uint32_t* bh = &Bh[nf >> 1][(nf & 1) * 2];
                    const uint32_t* bl = &Bl[nf >> 1][(nf & 1) * 2];
                    mma16816(C[mf][nf], Ah[mf], bh);   // hh
                    mma16816(C[mf][nf], Ah[mf], bl);   // hl
                    mma16816(C[mf][nf], Al[mf], bh);   // lh
                }
            }
        }

        __syncthreads();             // all warps done reading WBUF
        if (s < 5) {                 // stream next slab while epilogue runs
            const char* src = reinterpret_cast<const char*>(g_wslab[s + 1]);
            for (int i = tid; i < WSLAB_BYTES / 16; i += 256)
                cp16(smb + WBUF + i * 16, src + i * 16);
            cp_commit();
        }

        // ---- Epilogue: t[b][g][ot][p][d], d-contiguous float2 stores ----
        const int ot = s >> 1;
#pragma unroll
        for (int mf = 0; mf < 2; mf++) {
#pragma unroll
            for (int nf = 0; nf < 4; nf++) {
                const int p_l = wp * 32 + mf * 16 + gid;
                const int oo  = (s & 1) * 64 + wo * 32 + nf * 8 + tig * 2;
                const int g   = oo >> 5;
                const int d   = oo & 31;
                float* dst = g_t + (((size_t)(b * 4 + g) * 3 + ot) * PP + p0 + p_l) * 32 + d;
                *reinterpret_cast<float2*>(dst) = make_float2(C[mf][nf][0], C[mf][nf][1]);
                *reinterpret_cast<float2*>(dst + 8 * 32) = make_float2(C[mf][nf][2], C[mf][nf][3]);
            }
        }
    }
}

// ---------------------------------------------------------------------------
// Kernel B: 3x3 neighborhood attention, halo via cp.async (zero-fill OOB).
// CTA = 32x8 tile (warp = one full 32-x row -> full 128B store sectors),
// 256 threads; one 34x10x36f halo buffer reused K then V.
// Batch order reversed (b = 7 - blockIdx.z) for L2 reuse of freshest t.
// ---------------------------------------------------------------------------
static constexpr int TW = 32, TH = 8;      // tile width / height
static constexpr int HW = 34, HHALO = 10;  // halo width / height
static constexpr int HALO = HW * HHALO;    // 340
static constexpr int HPAD = 36;
static constexpr int ATT_SMEM = HALO * HPAD * 4;   // 48960 B

__device__ __forceinline__ void load_halo_async(uint32_t smb, const float* __restrict__ src,
                                                int ty0, int tx0, int tid) {
    for (int i = tid; i < HALO * 8; i += 256) {
        int pos = i >> 3, c = i & 7;
        int yy = pos / HW;
        int xx = pos - yy * HW;
        int gy = ty0 - 1 + yy;
        int gx = tx0 - 1 + xx;
        bool ok = (gy >= 0) && (gy < HH) && (gx >= 0) && (gx < WW);
        int cgy = ok ? gy : 0, cgx = ok ? gx : 0;    // clamped (unused if !ok)
        const float* sp = src + ((size_t)(cgy * WW + cgx)) * 32 + c * 4;
        cp16z(smb + (uint32_t)(pos * HPAD + c * 4) * 4, sp, ok);
    }
    cp_commit();
}

__global__ __launch_bounds__(256, 4) void attn_kernel(float* __restrict__ out) {
    extern __shared__ char smc[];
    float* smf = reinterpret_cast<float*>(smc);
    const uint32_t smb = smem_u32(smc);
    const int tid  = threadIdx.x;
    const int tile = blockIdx.x;               // 36 tiles: 3 x-wise, 12 y-wise
    const int ty0  = (tile / 3) * TH;
    const int tx0  = (tile % 3) * TW;
    const int g    = blockIdx.y;
    const int b    = (BATCH - 1) - blockIdx.z; // reversed: freshest t first
    const int tx = tid & 31;
    const int ty = tid >> 5;

    const size_t hb = (size_t)(b * 4 + g) * 3;
    const float* qb = g_t + (hb + 0) * PP * 32;
    const float* kb = g_t + (hb + 1) * PP * 32;
    const float* vb = g_t + (hb + 2) * PP * 32;

    load_halo_async(smb, kb, ty0, tx0, tid);     // K halo in flight

    const float* qp = qb + ((size_t)((ty0 + ty) * WW + tx0 + tx)) * 32;
    float4 q4[8];
#pragma unroll
    for (int j = 0; j < 8; j++) q4[j] = *reinterpret_cast<const float4*>(qp + 4 * j);

    int hp9[9];
#pragma unroll
    for (int n = 0; n < 9; n++) hp9[n] = (ty + n / 3) * HW + tx + (n % 3);

    cp_wait0();
    __syncthreads();

    float att[9];
#pragma unroll
    for (int n = 0; n < 9; n++) {
        const float* kp = smf + hp9[n] * HPAD;
        float sx = 0.f, sy = 0.f, sz = 0.f, sw = 0.f;
#pragma unroll
        for (int j = 0; j < 8; j++) {
            float4 kv = *reinterpret_cast<const float4*>(kp + 4 * j);
            sx = fmaf(q4[j].x, kv.x, sx);
            sy = fmaf(q4[j].y, kv.y, sy);
            sz = fmaf(q4[j].z, kv.z, sz);
            sw = fmaf(q4[j].w, kv.w, sw);
        }
        att[n] = ((sx + sy) + (sz + sw)) * RSQRT_D;
    }

    float m = att[0];
#pragma unroll
    for (int n = 1; n < 9; n++) m = fmaxf(m, att[n]);
    float ssum = 0.f;
#pragma unroll
    for (int n = 0; n < 9; n++) { att[n] = __expf(att[n] - m); ssum += att[n]; }
    float inv = 1.f / ssum;
#pragma unroll
    for (int n = 0; n < 9; n++) att[n] *= inv;

    __syncthreads();                 // everyone done reading K
    load_halo_async(smb, vb, ty0, tx0, tid);
    cp_wait0();
    __syncthreads();

    // out stores: warp = 32 consecutive x at one y-row -> full 128B sectors
    float* op = out + ((size_t)(b * CIN + g * 32)) * PP + (ty0 + ty) * WW + tx0 + tx;
#pragma unroll
    for (int j = 0; j < 8; j++) {
        float4 acc = make_float4(0.f, 0.f, 0.f, 0.f);
#pragma unroll
        for (int n = 0; n < 9; n++) {
            float4 vv = *reinterpret_cast<const float4*>(smf + hp9[n] * HPAD + 4 * j);
            acc.x = fmaf(att[n], vv.x, acc.x);
            acc.y = fmaf(att[n], vv.y, acc.y);
            acc.z = fmaf(att[n], vv.z, acc.z);
            acc.w = fmaf(att[n], vv.w, acc.w);
        }
        op[(size_t)(4 * j + 0) * PP] = acc.x;
        op[(size_t)(4 * j + 1) * PP] = acc.y;
        op[(size_t)(4 * j + 2) * PP] = acc.z;
        op[(size_t)(4 * j + 3) * PP] = acc.w;
    }
}

// ---------------------------------------------------------------------------
extern "C" void kernel_launch(void* const* d_in, const int* in_sizes, int n_in,
                              void* d_out, int out_size) {
    const float* x  = (const float*)d_in[0];   // [8,128,96,96]
    const float* Wt = (const float*)d_in[1];   // [384,128]
    float* out = (float*)d_out;                // [8,128,96,96]

    cudaFuncSetAttribute(qkv_mma,    cudaFuncAttributeMaxDynamicSharedMemorySize, GEMM_SMEM);
    cudaFuncSetAttribute(attn_kernel, cudaFuncAttributeMaxDynamicSharedMemorySize, ATT_SMEM);

    wprep_kernel<<<(384 * 64 + 255) / 256, 256>>>(Wt);
    qkv_mma<<<dim3(PP / 128, BATCH), 256, GEMM_SMEM>>>(x);
    attn_kernel<<<dim3((WW / TW) * (HH / TH), 4, BATCH), 256, ATT_SMEM>>>(out);
}

// round 16
// speedup vs baseline: 1.6617x; 1.5457x over previous
#include <cuda_runtime.h>
#include <cuda_bf16.h>
#include <cstdint>
#include <math.h>

// ---------------------------------------------------------------------------
// Problem constants
// ---------------------------------------------------------------------------
#define BATCH 8
#define CIN   128
#define HH    96
#define WW    96
#define PP    (HH*WW)          // 9216
#define RSQRT_D 0.17677669529663687f

// t layout: [b][g][qkv][p][d]  (d=32 contiguous per position)
__device__ float g_t[(size_t)BATCH * 384 * PP];

// Pre-split W in smem-image layout: [slab(6)][hi/lo(2)][64 rows x 136 bf16]
__device__ __nv_bfloat16 g_wslab[6][2][64 * 136];

// ---------------------------------------------------------------------------
// GEMM smem layout (single W buffer -> 102 KB -> 2 CTAs/SM)
// ---------------------------------------------------------------------------
static constexpr int TS   = 136;        // bf16 elems per row
static constexpr int TSB  = TS * 2;     // 272 bytes
static constexpr int XHI  = 0;                  // 34816 B
static constexpr int XLO  = 128 * TSB;          // 34816
static constexpr int WBUF = 2 * 128 * TSB;      // 69632 (hi 17408 | lo 17408)
static constexpr int WLO_OFF = 64 * TSB;        // 17408
static constexpr int WSLAB_BYTES = 2 * 64 * TSB;  // 34816
static constexpr int GEMM_SMEM = WBUF + WSLAB_BYTES; // 104448 B

__device__ __forceinline__ uint32_t smem_u32(const void* p) {
    uint32_t a;
    asm("{ .reg .u64 t; cvta.to.shared.u64 t, %1; cvt.u32.u64 %0, t; }" : "=r"(a) : "l"(p));
    return a;
}
__device__ __forceinline__ void ldm_x4(uint32_t r[4], uint32_t a) {
    asm volatile("ldmatrix.sync.aligned.m8n8.x4.shared.b16 {%0,%1,%2,%3}, [%4];"
                 : "=r"(r[0]), "=r"(r[1]), "=r"(r[2]), "=r"(r[3]) : "r"(a));
}
__device__ __forceinline__ void mma16816(float* c, const uint32_t* a, const uint32_t* b) {
    asm volatile("mma.sync.aligned.m16n8k16.row.col.f32.bf16.bf16.f32 "
                 "{%0,%1,%2,%3}, {%4,%5,%6,%7}, {%8,%9}, {%0,%1,%2,%3};"
                 : "+f"(c[0]), "+f"(c[1]), "+f"(c[2]), "+f"(c[3])
                 : "r"(a[0]), "r"(a[1]), "r"(a[2]), "r"(a[3]), "r"(b[0]), "r"(b[1]));
}
// L2-only (L1 bypass) 16B async copy: W slabs are consumed from smem, not L1.
__device__ __forceinline__ void cp16cg(uint32_t dst, const void* src) {
    asm volatile("cp.async.cg.shared.global [%0], [%1], 16;" :: "r"(dst), "l"(src));
}
// cp.async with src-size predication: sz=0 -> zero-fill (src not read)
__device__ __forceinline__ void cp16z(uint32_t dst, const void* src, bool ok) {
    int sz = ok ? 16 : 0;
    asm volatile("cp.async.ca.shared.global [%0], [%1], 16, %2;"
                 :: "r"(dst), "l"(src), "r"(sz));
}
__device__ __forceinline__ void cp_commit() {
    asm volatile("cp.async.commit_group;" ::: "memory");
}
__device__ __forceinline__ void cp_wait0() {
    asm volatile("cp.async.wait_group 0;" ::: "memory");
}
// split two fp32 into packed bf16x2 hi + lo (lo = residual)
__device__ __forceinline__ void split2(float f0, float f1, uint32_t& hi, uint32_t& lo) {
    __nv_bfloat16 h0 = __float2bfloat16(f0);
    __nv_bfloat16 h1 = __float2bfloat16(f1);
    __nv_bfloat16 l0 = __float2bfloat16(f0 - __bfloat162float(h0));
    __nv_bfloat16 l1 = __float2bfloat16(f1 - __bfloat162float(h1));
    hi = ((uint32_t)*reinterpret_cast<uint16_t*>(&h1) << 16) | *reinterpret_cast<uint16_t*>(&h0);
    lo = ((uint32_t)*reinterpret_cast<uint16_t*>(&l1) << 16) | *reinterpret_cast<uint16_t*>(&l0);
}

// ---------------------------------------------------------------------------
// Kernel 0: pre-split W into smem-image layout
// ---------------------------------------------------------------------------
__global__ void wprep_kernel(const float* __restrict__ Wt) {
    int i = blockIdx.x * 256 + threadIdx.x;      // over 384*64 channel-pairs
    if (i < 384 * 64) {
        int o = i >> 6, cp = i & 63;
        float2 w = *reinterpret_cast<const float2*>(&Wt[o * 128 + 2 * cp]);
        uint32_t hi, lo;
        split2(w.x, w.y, hi, lo);
        int slab = o >> 6, row = o & 63;
        reinterpret_cast<uint32_t*>(g_wslab[slab][0])[row * 68 + cp] = hi;
        reinterpret_cast<uint32_t*>(g_wslab[slab][1])[row * 68 + cp] = lo;
    }
}

// ---------------------------------------------------------------------------
// Kernel A: QKV GEMM via mma.sync bf16 (3-term hi/lo split, fp32 accum).
// Single W buffer, 2 CTAs/SM; W staging hidden by co-resident CTA.
// 8 warps = 4(p) x 2(o); warp tile 32p x 32o. Grid: (72, 8).
// ---------------------------------------------------------------------------
__global__ __launch_bounds__(256, 2) void qkv_mma(const float* __restrict__ x) {
    extern __shared__ char smc[];
    const uint32_t smb = smem_u32(smc);
    const int tid = threadIdx.x;
    const int p0  = blockIdx.x * 128;
    const int b   = blockIdx.y;

    // ---- Prologue: issue cp.async for W slab 0 ----
    {
        const char* src = reinterpret_cast<const char*>(g_wslab[0]);
        for (int i = tid; i < WSLAB_BYTES / 16; i += 256)
            cp16cg(smb + WBUF + i * 16, src + i * 16);
        cp_commit();
    }

    // ---- Stage X^T (hi/lo): thread handles half a p-row (64 channels) ----
    {
        const int row  = tid & 127;
        const int half = tid >> 7;
        const float* xp = x + (size_t)b * CIN * PP + p0 + row;
        uint32_t* xh = reinterpret_cast<uint32_t*>(smc + XHI + row * TSB + half * 128);
        uint32_t* xl = reinterpret_cast<uint32_t*>(smc + XLO + row * TSB + half * 128);
#pragma unroll
        for (int j = 0; j < 32; j++) {
            int c = half * 64 + 2 * j;
            float f0 = xp[(size_t)c * PP];
            float f1 = xp[(size_t)(c + 1) * PP];
            uint32_t hi, lo;
            split2(f0, f1, hi, lo);
            xh[j] = hi;
            xl[j] = lo;
        }
    }

    const int lane = tid & 31, wid = tid >> 5;
    const int wp = wid & 3;          // p: 4 x 32
    const int wo = wid >> 2;         // o: 2 x 32
    const int sel = lane >> 3, idx = lane & 7;
    const int gid = lane >> 2, tig = lane & 3;

    const uint32_t aoff = (uint32_t)((idx + (sel & 1) * 8) * TSB + (sel >> 1) * 16);
    const uint32_t boff = (uint32_t)((idx + (sel >> 1) * 8) * TSB + (sel & 1) * 16);
    const uint32_t aHi = smb + XHI + wp * 32 * TSB + aoff;
    const uint32_t aLo = smb + XLO + wp * 32 * TSB + aoff;
    const uint32_t bHi = smb + WBUF + wo * 32 * TSB + boff;
    const uint32_t bLo = bHi + WLO_OFF;

    for (int s = 0; s < 6; s++) {
        cp_wait0();
        __syncthreads();             // W slab visible to all warps (& X on s=0)

        float C[2][4][4];
#pragma unroll
        for (int mf = 0; mf < 2; mf++)
#pragma unroll
            for (int nf = 0; nf < 4; nf++)
#pragma unroll
                for (int r = 0; r < 4; r++) C[mf][nf][r] = 0.f;

#pragma unroll
        for (int ks = 0; ks < 8; ks++) {
            const uint32_t ko = ks * 32;
            uint32_t Ah[2][4], Al[2][4], Bh[2][4], Bl[2][4];
#pragma unroll
            for (int mf = 0; mf < 2; mf++) {
                ldm_x4(Ah[mf], aHi + mf * 16 * TSB + ko);
                ldm_x4(Al[mf], aLo + mf * 16 * TSB + ko);
            }
#pragma unroll
            for (int np = 0; np < 2; np++) {
                ldm_x4(Bh[np], bHi + np * 16 * TSB + ko);
                ldm_x4(Bl[np], bLo + np * 16 * TSB + ko);
            }
#pragma unroll
            for (int mf = 0; mf < 2; mf++) {
#pragma unroll
                for (int nf = 0; nf < 4; nf++) {
                    const uint32_t* bh = &Bh[nf >> 1][(nf & 1) * 2];
                    const uint32_t* bl = &Bl[nf >> 1][(nf & 1) * 2];
                    mma16816(C[mf][nf], Ah[mf], bh);   // hh
                    mma16816(C[mf][nf], Ah[mf], bl);   // hl
                    mma16816(C[mf][nf], Al[mf], bh);   // lh
                }
            }
        }

        __syncthreads();             // all warps done reading WBUF
        if (s < 5) {                 // stream next slab while epilogue runs
            const char* src = reinterpret_cast<const char*>(g_wslab[s + 1]);
            for (int i = tid; i < WSLAB_BYTES / 16; i += 256)
                cp16cg(smb + WBUF + i * 16, src + i * 16);
            cp_commit();
        }

        // ---- Epilogue: t[b][g][ot][p][d], d-contiguous float2 stores ----
        const int ot = s >> 1;
#pragma unroll
        for (int mf = 0; mf < 2; mf++) {
#pragma unroll
            for (int nf = 0; nf < 4; nf++) {
                const int p_l = wp * 32 + mf * 16 + gid;
                const int oo  = (s & 1) * 64 + wo * 32 + nf * 8 + tig * 2;
                const int g   = oo >> 5;
                const int d   = oo & 31;
                float* dst = g_t + (((size_t)(b * 4 + g) * 3 + ot) * PP + p0 + p_l) * 32 + d;
                *reinterpret_cast<float2*>(dst) = make_float2(C[mf][nf][0], C[mf][nf][1]);
                *reinterpret_cast<float2*>(dst + 8 * 32) = make_float2(C[mf][nf][2], C[mf][nf][3]);
            }
        }
    }
}

// ---------------------------------------------------------------------------
// Kernel B: 3x3 neighborhood attention, halo via cp.async (zero-fill OOB).
// CTA = 32x8 tile, 256 threads; one 34x10x36f halo buffer reused K then V.
// V halo issued immediately after K reads complete; softmax overlaps the fill.
// ---------------------------------------------------------------------------
static constexpr int TW = 32, TH = 8;      // tile width / height
static constexpr int HW = 34, HHALO = 10;  // halo width / height
static constexpr int HALO = HW * HHALO;    // 340
static constexpr int HPAD = 36;
static constexpr int ATT_SMEM = HALO * HPAD * 4;   // 48960 B

__device__ __forceinline__ void load_halo_async(uint32_t smb, const float* __restrict__ src,
                                                int ty0, int tx0, int tid) {
    for (int i = tid; i < HALO * 8; i += 256) {
        int pos = i >> 3, c = i & 7;
        int yy = pos / HW;
        int xx = pos - yy * HW;
        int gy = ty0 - 1 + yy;
        int gx = tx0 - 1 + xx;
        bool ok = (gy >= 0) && (gy < HH) && (gx >= 0) && (gx < WW);
        int cgy = ok ? gy : 0, cgx = ok ? gx : 0;    // clamped (unused if !ok)
        const float* sp = src + ((size_t)(cgy * WW + cgx)) * 32 + c * 4;
        cp16z(smb + (uint32_t)(pos * HPAD + c * 4) * 4, sp, ok);
    }
    cp_commit();
}

__global__ __launch_bounds__(256, 4) void attn_kernel(float* __restrict__ out) {
    extern __shared__ char smc[];
    float* smf = reinterpret_cast<float*>(smc);
    const uint32_t smb = smem_u32(smc);
    const int tid  = threadIdx.x;
    const int tile = blockIdx.x;               // 36 tiles: 3 x-wise, 12 y-wise
    const int ty0  = (tile / 3) * TH;
    const int tx0  = (tile % 3) * TW;
    const int g    = blockIdx.y;
    const int b    = (BATCH - 1) - blockIdx.z; // reversed: freshest t first
    const int tx = tid & 31;
    const int ty = tid >> 5;

    const size_t hb = (size_t)(b * 4 + g) * 3;
    const float* qb = g_t + (hb + 0) * PP * 32;
    const float* kb = g_t + (hb + 1) * PP * 32;
    const float* vb = g_t + (hb + 2) * PP * 32;

    load_halo_async(smb, kb, ty0, tx0, tid);     // K halo in flight

    const float* qp = qb + ((size_t)((ty0 + ty) * WW + tx0 + tx)) * 32;
    float4 q4[8];
#pragma unroll
    for (int j = 0; j < 8; j++) q4[j] = *reinterpret_cast<const float4*>(qp + 4 * j);

    int hp9[9];
#pragma unroll
    for (int n = 0; n < 9; n++) hp9[n] = (ty + n / 3) * HW + tx + (n % 3);

    cp_wait0();
    __syncthreads();

    float att[9];
#pragma unroll
    for (int n = 0; n < 9; n++) {
        const float* kp = smf + hp9[n] * HPAD;
        float sx = 0.f, sy = 0.f, sz = 0.f, sw = 0.f;
#pragma unroll
        for (int j = 0; j < 8; j++) {
            float4 kv = *reinterpret_cast<const float4*>(kp + 4 * j);
            sx = fmaf(q4[j].x, kv.x, sx);
            sy = fmaf(q4[j].y, kv.y, sy);
            sz = fmaf(q4[j].z, kv.z, sz);
            sw = fmaf(q4[j].w, kv.w, sw);
        }
        att[n] = ((sx + sy) + (sz + sw)) * RSQRT_D;
    }

    // All K reads done -> safe to start refilling the buffer with V while
    // the softmax arithmetic below runs (overlap cp.async with math).
    __syncthreads();
    load_halo_async(smb, vb, ty0, tx0, tid);

    float m = att[0];
#pragma unroll
    for (int n = 1; n < 9; n++) m = fmaxf(m, att[n]);
    float ssum = 0.f;
#pragma unroll
    for (int n = 0; n < 9; n++) { att[n] = __expf(att[n] - m); ssum += att[n]; }
    float inv = 1.f / ssum;
#pragma unroll
    for (int n = 0; n < 9; n++) att[n] *= inv;

    cp_wait0();
    __syncthreads();

    // out stores: warp = 32 consecutive x at one y-row -> full 128B sectors
    float* op = out + ((size_t)(b * CIN + g * 32)) * PP + (ty0 + ty) * WW + tx0 + tx;
#pragma unroll
    for (int j = 0; j < 8; j++) {
        float4 acc = make_float4(0.f, 0.f, 0.f, 0.f);
#pragma unroll
        for (int n = 0; n < 9; n++) {
            float4 vv = *reinterpret_cast<const float4*>(smf + hp9[n] * HPAD + 4 * j);
            acc.x = fmaf(att[n], vv.x, acc.x);
            acc.y = fmaf(att[n], vv.y, acc.y);
            acc.z = fmaf(att[n], vv.z, acc.z);
            acc.w = fmaf(att[n], vv.w, acc.w);
        }
        op[(size_t)(4 * j + 0) * PP] = acc.x;
        op[(size_t)(4 * j + 1) * PP] = acc.y;
        op[(size_t)(4 * j + 2) * PP] = acc.z;
        op[(size_t)(4 * j + 3) * PP] = acc.w;
    }
}

// ---------------------------------------------------------------------------
extern "C" void kernel_launch(void* const* d_in, const int* in_sizes, int n_in,
                              void* d_out, int out_size) {
    const float* x  = (const float*)d_in[0];   // [8,128,96,96]
    const float* Wt = (const float*)d_in[1];   // [384,128]
    float* out = (float*)d_out;                // [8,128,96,96]

    cudaFuncSetAttribute(qkv_mma,    cudaFuncAttributeMaxDynamicSharedMemorySize, GEMM_SMEM);
    cudaFuncSetAttribute(attn_kernel, cudaFuncAttributeMaxDynamicSharedMemorySize, ATT_SMEM);

    wprep_kernel<<<(384 * 64 + 255) / 256, 256>>>(Wt);
    qkv_mma<<<dim3(PP / 128, BATCH), 256, GEMM_SMEM>>>(x);
    attn_kernel<<<dim3((WW / TW) * (HH / TH), 4, BATCH), 256, ATT_SMEM>>>(out);
}